// round 6
// baseline (speedup 1.0000x reference)
#include <cuda_runtime.h>

#define NN 50000
#define NE 800000

typedef unsigned int u32;
typedef unsigned long long u64;

// ---------------------------------------------------------------------------
// Device scratch (no cudaMalloc allowed)
// ---------------------------------------------------------------------------
__device__ float g_agg[(size_t)NN * 128];
// Pre-split bf16 weights, transposed to [n][k], row stride 272B,
// per 128-K chunk: [hi 34816 B][lo 34816 B] = 69632 B.
#define WCHUNK 69632
__device__ __align__(16) unsigned char g_we[5 * WCHUNK]; // edge: L1 x3, L2, L3
__device__ __align__(16) unsigned char g_wn[4 * WCHUNK]; // node: L1 x2, L2, L3

// ---------------------------------------------------------------------------
// SMEM layout: A_hi/A_lo are 256 rows; B_hi/B_lo 128 rows; row stride 272 B.
// ---------------------------------------------------------------------------
#define ROWB 272
#define ATILE (256 * ROWB)   // 69632
#define BTILE (128 * ROWB)   // 34816
#define SM_AHI 0
#define SM_ALO ATILE
#define SM_BHI (2 * ATILE)           // 139264
#define SM_BLO (2 * ATILE + BTILE)   // 174080
#define SM_BYTES (2 * ATILE + 2 * BTILE) // 208896

#define MROWS 256
#define NTHREADS 512

// ---------------------------------------------------------------------------
// Helpers
// ---------------------------------------------------------------------------
__device__ __forceinline__ u32 smem_u32(const void* p) {
    u32 a;
    asm("{ .reg .u64 t; cvta.to.shared.u64 t, %1; cvt.u32.u64 %0, t; }"
        : "=r"(a) : "l"(p));
    return a;
}
// packs e0 into LOW half, e1 into HIGH half
__device__ __forceinline__ u32 pack_bf16x2(float e0, float e1) {
    u32 r;
    asm("cvt.rn.bf16x2.f32 %0, %1, %2;" : "=r"(r) : "f"(e1), "f"(e0));
    return r;
}
__device__ __forceinline__ float bf_lo_f(u32 p) { return __uint_as_float(p << 16); }
__device__ __forceinline__ float bf_hi_f(u32 p) { return __uint_as_float(p & 0xffff0000u); }
__device__ __forceinline__ float silu_f(float v) { return __fdividef(v, 1.0f + __expf(-v)); }

__device__ __forceinline__ void ldsm4(u32& r0, u32& r1, u32& r2, u32& r3, u32 addr) {
    asm volatile("ldmatrix.sync.aligned.m8n8.x4.shared.b16 {%0,%1,%2,%3}, [%4];"
                 : "=r"(r0), "=r"(r1), "=r"(r2), "=r"(r3) : "r"(addr));
}
__device__ __forceinline__ void mma16816(float* c, const u32* a, u32 b0, u32 b1) {
    asm volatile(
        "mma.sync.aligned.m16n8k16.row.col.f32.bf16.bf16.f32 "
        "{%0,%1,%2,%3}, {%4,%5,%6,%7}, {%8,%9}, {%0,%1,%2,%3};"
        : "+f"(c[0]), "+f"(c[1]), "+f"(c[2]), "+f"(c[3])
        : "r"(a[0]), "r"(a[1]), "r"(a[2]), "r"(a[3]), "r"(b0), "r"(b1));
}

__device__ __forceinline__ void split4(float v0, float v1, float v2, float v3,
                                       u64& hi, u64& lo) {
    u32 h0 = pack_bf16x2(v0, v1), h1 = pack_bf16x2(v2, v3);
    u32 l0 = pack_bf16x2(v0 - bf_lo_f(h0), v1 - bf_hi_f(h0));
    u32 l1 = pack_bf16x2(v2 - bf_lo_f(h1), v3 - bf_hi_f(h1));
    hi = (u64)h0 | ((u64)h1 << 32);
    lo = (u64)l0 | ((u64)l1 << 32);
}

// ---------------------------------------------------------------------------
// Per-warp GEMM over one 128-K chunk with 3-term bf16 split.
// acc[2][8][4]: warp tile 32 rows x 64 cols.
// ---------------------------------------------------------------------------
__device__ __forceinline__ void chunk_mma(char* sm, float acc[2][8][4],
                                          int mbase, int nbase, int lane) {
    const u32 smb = smem_u32(sm);
    const u32 a_off = (u32)(mbase + (lane & 15)) * ROWB + (u32)(lane >> 4) * 16;
    const u32 b_off = (u32)(nbase + (lane & 7) + ((lane >> 4) & 1) * 8) * ROWB
                    + (u32)((lane >> 3) & 1) * 16;
#pragma unroll
    for (int ks = 0; ks < 8; ++ks) {
        const u32 kb = (u32)ks * 32;
        u32 ah[2][4], al[2][4], b[4][4];
#pragma unroll
        for (int mg = 0; mg < 2; ++mg)
            ldsm4(ah[mg][0], ah[mg][1], ah[mg][2], ah[mg][3],
                  smb + SM_AHI + a_off + (u32)mg * (16 * ROWB) + kb);
#pragma unroll
        for (int g = 0; g < 4; ++g)
            ldsm4(b[g][0], b[g][1], b[g][2], b[g][3],
                  smb + SM_BHI + b_off + (u32)g * (16 * ROWB) + kb);
        // hh
#pragma unroll
        for (int mg = 0; mg < 2; ++mg)
#pragma unroll
            for (int ng = 0; ng < 8; ++ng)
                mma16816(acc[mg][ng], ah[mg], b[ng >> 1][(ng & 1) * 2], b[ng >> 1][(ng & 1) * 2 + 1]);
        // lh
#pragma unroll
        for (int mg = 0; mg < 2; ++mg)
            ldsm4(al[mg][0], al[mg][1], al[mg][2], al[mg][3],
                  smb + SM_ALO + a_off + (u32)mg * (16 * ROWB) + kb);
#pragma unroll
        for (int mg = 0; mg < 2; ++mg)
#pragma unroll
            for (int ng = 0; ng < 8; ++ng)
                mma16816(acc[mg][ng], al[mg], b[ng >> 1][(ng & 1) * 2], b[ng >> 1][(ng & 1) * 2 + 1]);
        // hl (reload B from lo tile, reuse ah)
#pragma unroll
        for (int g = 0; g < 4; ++g)
            ldsm4(b[g][0], b[g][1], b[g][2], b[g][3],
                  smb + SM_BLO + b_off + (u32)g * (16 * ROWB) + kb);
#pragma unroll
        for (int mg = 0; mg < 2; ++mg)
#pragma unroll
            for (int ng = 0; ng < 8; ++ng)
                mma16816(acc[mg][ng], ah[mg], b[ng >> 1][(ng & 1) * 2], b[ng >> 1][(ng & 1) * 2 + 1]);
    }
}

// Copy one pre-split weight chunk (hi+lo, 69632 B) to B smem. 512 threads.
__device__ __forceinline__ void fill_B(char* sm, const unsigned char* w, int tid) {
    const int4* s = (const int4*)w;
    int4* d = (int4*)(sm + SM_BHI);
#pragma unroll
    for (int i = 0; i < 9; ++i) {
        int t = tid + i * NTHREADS;
        if (t < WCHUNK / 16) d[t] = s[t];
    }
}

// bias + SiLU from acc -> A smem (hi/lo), zero acc
__device__ __forceinline__ void mid_epi(char* sm, float acc[2][8][4],
                                        const float* __restrict__ bias,
                                        int mbase, int nbase, int lane) {
    const int q = lane & 3, r = lane >> 2;
#pragma unroll
    for (int mg = 0; mg < 2; ++mg) {
#pragma unroll
        for (int ng = 0; ng < 8; ++ng) {
            const int col = nbase + ng * 8 + q * 2;
            const float bx = __ldg(bias + col), by = __ldg(bias + col + 1);
            const int r0 = mbase + mg * 16 + r, r1 = r0 + 8;
            float v0 = silu_f(acc[mg][ng][0] + bx);
            float v1 = silu_f(acc[mg][ng][1] + by);
            float v2 = silu_f(acc[mg][ng][2] + bx);
            float v3 = silu_f(acc[mg][ng][3] + by);
            u32 h0 = pack_bf16x2(v0, v1);
            u32 l0 = pack_bf16x2(v0 - bf_lo_f(h0), v1 - bf_hi_f(h0));
            u32 h1 = pack_bf16x2(v2, v3);
            u32 l1 = pack_bf16x2(v2 - bf_lo_f(h1), v3 - bf_hi_f(h1));
            *(u32*)(sm + SM_AHI + r0 * ROWB + col * 2) = h0;
            *(u32*)(sm + SM_ALO + r0 * ROWB + col * 2) = l0;
            *(u32*)(sm + SM_AHI + r1 * ROWB + col * 2) = h1;
            *(u32*)(sm + SM_ALO + r1 * ROWB + col * 2) = l1;
            acc[mg][ng][0] = 0.f; acc[mg][ng][1] = 0.f;
            acc[mg][ng][2] = 0.f; acc[mg][ng][3] = 0.f;
        }
    }
}

#define SVS 130  // float stride of epilogue scratch rows (256*130*4 = 133120 <= 2*ATILE)

__device__ __forceinline__ void final_dump(char* sm, float acc[2][8][4],
                                           const float* __restrict__ b3,
                                           int mbase, int nbase, int lane) {
    float* sv = (float*)sm;
    const int q = lane & 3, r = lane >> 2;
#pragma unroll
    for (int mg = 0; mg < 2; ++mg) {
#pragma unroll
        for (int ng = 0; ng < 8; ++ng) {
            const int col = nbase + ng * 8 + q * 2;
            const float bx = __ldg(b3 + col), by = __ldg(b3 + col + 1);
            const int r0 = mbase + mg * 16 + r, r1 = r0 + 8;
            *(float2*)(sv + r0 * SVS + col) = make_float2(acc[mg][ng][0] + bx, acc[mg][ng][1] + by);
            *(float2*)(sv + r1 * SVS + col) = make_float2(acc[mg][ng][2] + bx, acc[mg][ng][3] + by);
        }
    }
}

// per-row mean/rstd; stats stored in B region (dead by then)
__device__ __forceinline__ void ln_stats(char* sm, int tid) {
    if (tid < MROWS) {
        const float* sv = (float*)sm;
        float s1 = 0.f, s2 = 0.f;
#pragma unroll 16
        for (int c = 0; c < 128; c += 2) {
            float2 v = *(const float2*)(sv + tid * SVS + c);
            s1 += v.x + v.y;
            s2 += v.x * v.x + v.y * v.y;
        }
        float mean = s1 * (1.0f / 128.0f);
        float var = s2 * (1.0f / 128.0f) - mean * mean;
        ((float*)(sm + SM_BHI))[tid] = mean;
        ((float*)(sm + SM_BHI + 1024))[tid] = rsqrtf(var + 1e-5f);
    }
}

// ---------------------------------------------------------------------------
// Edge kernel: 256 edges/block, 512 threads (16 warps)
// ---------------------------------------------------------------------------
__global__ __launch_bounds__(NTHREADS, 1)
void edge_kernel(const float* __restrict__ x, const int* __restrict__ eidx,
                 const float* __restrict__ ea,
                 const float* __restrict__ b1, const float* __restrict__ b2,
                 const float* __restrict__ b3,
                 const float* __restrict__ gw, const float* __restrict__ bw,
                 float* __restrict__ out_e) {
    extern __shared__ char sm[];
    const int tid = threadIdx.x, wid = tid >> 5, lane = tid & 31;
    const int mbase = (wid >> 1) * 32, nbase = (wid & 1) * 64;
    const int e0 = blockIdx.x * MROWS;

    float acc[2][8][4];
#pragma unroll
    for (int mg = 0; mg < 2; ++mg)
#pragma unroll
        for (int ng = 0; ng < 8; ++ng)
#pragma unroll
            for (int k = 0; k < 4; ++k) acc[mg][ng][k] = 0.f;

    // ---- layer 1: 3 accumulated K=128 chunks (x[i], x[j], edge_attr) ----
    for (int s = 0; s < 3; ++s) {
        const int row = tid >> 1, qb = (tid & 1) * 16;
        const int g = (s == 0) ? __ldg(eidx + e0 + row)
                    : (s == 1) ? __ldg(eidx + NE + e0 + row)
                               : (e0 + row);
        const float4* src = (s == 2) ? (const float4*)ea : (const float4*)x;
#pragma unroll 4
        for (int i = 0; i < 16; ++i) {
            float4 v = __ldg(src + (size_t)g * 32 + qb + i);
            u64 hi, lo;
            split4(v.x, v.y, v.z, v.w, hi, lo);
            *(u64*)(sm + SM_AHI + row * ROWB + (qb + i) * 8) = hi;
            *(u64*)(sm + SM_ALO + row * ROWB + (qb + i) * 8) = lo;
        }
        fill_B(sm, g_we + (size_t)s * WCHUNK, tid);
        __syncthreads();
        chunk_mma(sm, acc, mbase, nbase, lane);
        __syncthreads();
    }

    // ---- layer 2 ----
    mid_epi(sm, acc, b1, mbase, nbase, lane);
    fill_B(sm, g_we + 3 * WCHUNK, tid);
    __syncthreads();
    chunk_mma(sm, acc, mbase, nbase, lane);
    __syncthreads();

    // ---- layer 3 ----
    mid_epi(sm, acc, b2, mbase, nbase, lane);
    fill_B(sm, g_we + 4 * WCHUNK, tid);
    __syncthreads();
    chunk_mma(sm, acc, mbase, nbase, lane);
    __syncthreads();

    // ---- final: bias3 -> LN -> residual -> store + scatter ----
    final_dump(sm, acc, b3, mbase, nbase, lane);
    __syncthreads();
    ln_stats(sm, tid);
    __syncthreads();

    {
        const int tc = tid & 15, tr = tid >> 4;   // tr 0..31
        const float* sv = (const float*)sm;
        const float* smean = (const float*)(sm + SM_BHI);
        const float* srstd = (const float*)(sm + SM_BHI + 1024);
        float gv[8], bv[8];
#pragma unroll
        for (int j = 0; j < 8; ++j) {
            gv[j] = __ldg(gw + tc * 8 + j);
            bv[j] = __ldg(bw + tc * 8 + j);
        }
        // 512 threads x 8 iters: rows 0..255, 16 col-groups
        for (int r8 = 0; r8 < 8; ++r8) {
            const int row = r8 * 32 + tr;
            const long long gr = e0 + row;
            const float mean = smean[row], rstd = srstd[row];
            float4 ra = __ldg((const float4*)ea + gr * 32 + tc * 2);
            float4 rb = __ldg((const float4*)ea + gr * 32 + tc * 2 + 1);
            float o[8];
#pragma unroll
            for (int j = 0; j < 8; ++j)
                o[j] = (sv[row * SVS + tc * 8 + j] - mean) * rstd * gv[j] + bv[j];
            o[0] += ra.x; o[1] += ra.y; o[2] += ra.z; o[3] += ra.w;
            o[4] += rb.x; o[5] += rb.y; o[6] += rb.z; o[7] += rb.w;
            ((float4*)out_e)[gr * 32 + tc * 2]     = make_float4(o[0], o[1], o[2], o[3]);
            ((float4*)out_e)[gr * 32 + tc * 2 + 1] = make_float4(o[4], o[5], o[6], o[7]);
            const int dj = __ldg(eidx + NE + gr);
            float* ap = g_agg + (size_t)dj * 128 + tc * 8;
#pragma unroll
            for (int j = 0; j < 8; ++j) atomicAdd(ap + j, o[j]);
        }
    }
}

// ---------------------------------------------------------------------------
// Node kernel: 256 nodes/block, 512 threads
// ---------------------------------------------------------------------------
__global__ __launch_bounds__(NTHREADS, 1)
void node_kernel(const float* __restrict__ x,
                 const float* __restrict__ b1, const float* __restrict__ b2,
                 const float* __restrict__ b3,
                 const float* __restrict__ gw, const float* __restrict__ bw,
                 float* __restrict__ out_x) {
    extern __shared__ char sm[];
    const int tid = threadIdx.x, wid = tid >> 5, lane = tid & 31;
    const int mbase = (wid >> 1) * 32, nbase = (wid & 1) * 64;
    const int n0 = blockIdx.x * MROWS;

    float acc[2][8][4];
#pragma unroll
    for (int mg = 0; mg < 2; ++mg)
#pragma unroll
        for (int ng = 0; ng < 8; ++ng)
#pragma unroll
            for (int k = 0; k < 4; ++k) acc[mg][ng][k] = 0.f;

    // ---- layer 1: 2 accumulated K=128 chunks (x, agg) ----
    for (int s = 0; s < 2; ++s) {
        const float4* src = (s == 0) ? (const float4*)x : (const float4*)g_agg;
        const int row = tid >> 1, qb = (tid & 1) * 16;
        const int g = n0 + row;
#pragma unroll 4
        for (int i = 0; i < 16; ++i) {
            float4 v = make_float4(0.f, 0.f, 0.f, 0.f);
            if (g < NN) v = __ldg(src + (size_t)g * 32 + qb + i);
            u64 hi, lo;
            split4(v.x, v.y, v.z, v.w, hi, lo);
            *(u64*)(sm + SM_AHI + row * ROWB + (qb + i) * 8) = hi;
            *(u64*)(sm + SM_ALO + row * ROWB + (qb + i) * 8) = lo;
        }
        fill_B(sm, g_wn + (size_t)s * WCHUNK, tid);
        __syncthreads();
        chunk_mma(sm, acc, mbase, nbase, lane);
        __syncthreads();
    }

    mid_epi(sm, acc, b1, mbase, nbase, lane);
    fill_B(sm, g_wn + 2 * WCHUNK, tid);
    __syncthreads();
    chunk_mma(sm, acc, mbase, nbase, lane);
    __syncthreads();

    mid_epi(sm, acc, b2, mbase, nbase, lane);
    fill_B(sm, g_wn + 3 * WCHUNK, tid);
    __syncthreads();
    chunk_mma(sm, acc, mbase, nbase, lane);
    __syncthreads();

    final_dump(sm, acc, b3, mbase, nbase, lane);
    __syncthreads();
    ln_stats(sm, tid);
    __syncthreads();

    {
        const int tc = tid & 15, tr = tid >> 4;
        const float* sv = (const float*)sm;
        const float* smean = (const float*)(sm + SM_BHI);
        const float* srstd = (const float*)(sm + SM_BHI + 1024);
        float gv[8], bv[8];
#pragma unroll
        for (int j = 0; j < 8; ++j) {
            gv[j] = __ldg(gw + tc * 8 + j);
            bv[j] = __ldg(bw + tc * 8 + j);
        }
        for (int r8 = 0; r8 < 8; ++r8) {
            const int row = r8 * 32 + tr;
            const long long gr = n0 + row;
            if (gr < NN) {
                const float mean = smean[row], rstd = srstd[row];
                float4 ra = __ldg((const float4*)x + gr * 32 + tc * 2);
                float4 rb = __ldg((const float4*)x + gr * 32 + tc * 2 + 1);
                float o[8];
#pragma unroll
                for (int j = 0; j < 8; ++j)
                    o[j] = (sv[row * SVS + tc * 8 + j] - mean) * rstd * gv[j] + bv[j];
                o[0] += ra.x; o[1] += ra.y; o[2] += ra.z; o[3] += ra.w;
                o[4] += rb.x; o[5] += rb.y; o[6] += rb.z; o[7] += rb.w;
                ((float4*)out_x)[gr * 32 + tc * 2]     = make_float4(o[0], o[1], o[2], o[3]);
                ((float4*)out_x)[gr * 32 + tc * 2 + 1] = make_float4(o[4], o[5], o[6], o[7]);
            }
        }
    }
}

// ---------------------------------------------------------------------------
// Weight prep: split into bf16 hi/lo, transpose to [n][k], row stride 272B.
// ---------------------------------------------------------------------------
__global__ void prep_w(const float* __restrict__ ew1, const float* __restrict__ ew2,
                       const float* __restrict__ ew3, const float* __restrict__ nw1,
                       const float* __restrict__ nw2, const float* __restrict__ nw3) {
    int i = blockIdx.x * blockDim.x + threadIdx.x;
    if (i >= 9 * 16384) return;
    unsigned char* dst;
    float val;
    int cs = i >> 14, r = i & 16383;
    int kl = r >> 7, n = r & 127;
    if (cs < 5) {
        if (cs < 3)       val = ew1[(cs * 128 + kl) * 128 + n];
        else if (cs == 3) val = ew2[kl * 128 + n];
        else              val = ew3[kl * 128 + n];
        dst = g_we + (size_t)cs * WCHUNK;
    } else {
        int ns = cs - 5;
        if (ns < 2)       val = nw1[(ns * 128 + kl) * 128 + n];
        else if (ns == 2) val = nw2[kl * 128 + n];
        else              val = nw3[kl * 128 + n];
        dst = g_wn + (size_t)ns * WCHUNK;
    }
    u32 h = pack_bf16x2(val, 0.f);
    u32 l = pack_bf16x2(val - bf_lo_f(h), 0.f);
    *(unsigned short*)(dst + n * ROWB + kl * 2)         = (unsigned short)(h & 0xffff);
    *(unsigned short*)(dst + BTILE + n * ROWB + kl * 2) = (unsigned short)(l & 0xffff);
}

__global__ void zero_agg_kernel() {
    int i = blockIdx.x * blockDim.x + threadIdx.x;
    if (i < NN * 32)
        ((float4*)g_agg)[i] = make_float4(0.f, 0.f, 0.f, 0.f);
}

// ---------------------------------------------------------------------------
extern "C" void kernel_launch(void* const* d_in, const int* in_sizes, int n_in,
                              void* d_out, int out_size) {
    const float* x    = (const float*)d_in[0];
    const int*   eidx = (const int*)d_in[1];
    const float* ea   = (const float*)d_in[2];
    const float* ew1  = (const float*)d_in[3];
    const float* eb1  = (const float*)d_in[4];
    const float* ew2  = (const float*)d_in[5];
    const float* eb2  = (const float*)d_in[6];
    const float* ew3  = (const float*)d_in[7];
    const float* eb3  = (const float*)d_in[8];
    const float* eg   = (const float*)d_in[9];
    const float* ebt  = (const float*)d_in[10];
    const float* nw1  = (const float*)d_in[11];
    const float* nb1  = (const float*)d_in[12];
    const float* nw2  = (const float*)d_in[13];
    const float* nb2  = (const float*)d_in[14];
    const float* nw3  = (const float*)d_in[15];
    const float* nb3  = (const float*)d_in[16];
    const float* ng   = (const float*)d_in[17];
    const float* nbt  = (const float*)d_in[18];

    float* out_x = (float*)d_out;                       // [50000, 128]
    float* out_e = (float*)d_out + (size_t)NN * 128;    // [800000, 128]

    cudaFuncSetAttribute(edge_kernel, cudaFuncAttributeMaxDynamicSharedMemorySize, SM_BYTES);
    cudaFuncSetAttribute(node_kernel, cudaFuncAttributeMaxDynamicSharedMemorySize, SM_BYTES);

    zero_agg_kernel<<<(NN * 32 + 255) / 256, 256>>>();
    prep_w<<<(9 * 16384 + 255) / 256, 256>>>(ew1, ew2, ew3, nw1, nw2, nw3);
    edge_kernel<<<NE / MROWS, NTHREADS, SM_BYTES>>>(x, eidx, ea, eb1, eb2, eb3, eg, ebt, out_e);
    node_kernel<<<(NN + MROWS - 1) / MROWS, NTHREADS, SM_BYTES>>>(x, nb1, nb2, nb3, ng, nbt, out_x);
}

// round 7
// speedup vs baseline: 1.0266x; 1.0266x over previous
#include <cuda_runtime.h>

#define NN 50000
#define NE 800000

typedef unsigned int u32;
typedef unsigned long long u64;

// ---------------------------------------------------------------------------
// Device scratch (no cudaMalloc allowed)
// ---------------------------------------------------------------------------
__device__ float g_agg[(size_t)NN * 128];
// Pre-split bf16 weights, transposed to [n][k], row stride 272B,
// per 128-K chunk: [hi 34816 B][lo 34816 B] = 69632 B.
#define WCHUNK 69632
__device__ __align__(16) unsigned char g_we[5 * WCHUNK]; // edge: L1 x3, L2, L3
__device__ __align__(16) unsigned char g_wn[4 * WCHUNK]; // node: L1 x2, L2, L3

// ---------------------------------------------------------------------------
// SMEM: A_hi, A_lo (128 rows each), B double buffer (2 x (hi+lo)).
// ---------------------------------------------------------------------------
#define ROWB 272
#define BTILE 34816              // 128 * 272
#define SM_AHI 0
#define SM_ALO BTILE             // 34816
#define SM_B0  (2 * BTILE)       // 69632
#define SM_B1  (4 * BTILE)       // 139264
#define SM_BYTES (6 * BTILE)     // 208896

#define MROWS 128
#define NTHREADS 256

// ---------------------------------------------------------------------------
// Helpers
// ---------------------------------------------------------------------------
__device__ __forceinline__ u32 smem_u32(const void* p) {
    u32 a;
    asm("{ .reg .u64 t; cvta.to.shared.u64 t, %1; cvt.u32.u64 %0, t; }"
        : "=r"(a) : "l"(p));
    return a;
}
__device__ __forceinline__ u32 pack_bf16x2(float e0, float e1) {
    u32 r;
    asm("cvt.rn.bf16x2.f32 %0, %1, %2;" : "=r"(r) : "f"(e1), "f"(e0));
    return r;
}
__device__ __forceinline__ float bf_lo_f(u32 p) { return __uint_as_float(p << 16); }
__device__ __forceinline__ float bf_hi_f(u32 p) { return __uint_as_float(p & 0xffff0000u); }
__device__ __forceinline__ float silu_f(float v) { return __fdividef(v, 1.0f + __expf(-v)); }

__device__ __forceinline__ void ldsm4(u32& r0, u32& r1, u32& r2, u32& r3, u32 addr) {
    asm volatile("ldmatrix.sync.aligned.m8n8.x4.shared.b16 {%0,%1,%2,%3}, [%4];"
                 : "=r"(r0), "=r"(r1), "=r"(r2), "=r"(r3) : "r"(addr));
}
__device__ __forceinline__ void mma16816(float* c, const u32* a, u32 b0, u32 b1) {
    asm volatile(
        "mma.sync.aligned.m16n8k16.row.col.f32.bf16.bf16.f32 "
        "{%0,%1,%2,%3}, {%4,%5,%6,%7}, {%8,%9}, {%0,%1,%2,%3};"
        : "+f"(c[0]), "+f"(c[1]), "+f"(c[2]), "+f"(c[3])
        : "r"(a[0]), "r"(a[1]), "r"(a[2]), "r"(a[3]), "r"(b0), "r"(b1));
}
__device__ __forceinline__ void split4(float v0, float v1, float v2, float v3,
                                       u64& hi, u64& lo) {
    u32 h0 = pack_bf16x2(v0, v1), h1 = pack_bf16x2(v2, v3);
    u32 l0 = pack_bf16x2(v0 - bf_lo_f(h0), v1 - bf_hi_f(h0));
    u32 l1 = pack_bf16x2(v2 - bf_lo_f(h1), v3 - bf_hi_f(h1));
    hi = (u64)h0 | ((u64)h1 << 32);
    lo = (u64)l0 | ((u64)l1 << 32);
}

// ---- cp.async ----
__device__ __forceinline__ void cp16(u32 dst, const void* src) {
    asm volatile("cp.async.cg.shared.global [%0], [%1], 16;" :: "r"(dst), "l"(src));
}
#define CP_COMMIT() asm volatile("cp.async.commit_group;" ::: "memory")
#define CP_WAIT(n)  asm volatile("cp.async.wait_group %0;" :: "n"(n) : "memory")

// Async prefetch of one weight chunk (hi+lo, 69632 B = 4352 x 16B) into smem.
__device__ __forceinline__ void fill_B_async(u32 dst, const unsigned char* w, int tid) {
#pragma unroll
    for (int i = 0; i < 17; ++i) {
        int t = tid + i * NTHREADS;
        cp16(dst + t * 16, w + t * 16);
    }
}

// ---------------------------------------------------------------------------
// Per-warp GEMM over one 128-K chunk, 3-term bf16 split. Warp tile 32x64.
// ---------------------------------------------------------------------------
__device__ __forceinline__ void chunk_mma(u32 smb, u32 bbase, float acc[2][8][4],
                                          int mbase, int nbase, int lane) {
    const u32 a_off = (u32)(mbase + (lane & 15)) * ROWB + (u32)(lane >> 4) * 16;
    const u32 b_off = (u32)(nbase + (lane & 7) + ((lane >> 4) & 1) * 8) * ROWB
                    + (u32)((lane >> 3) & 1) * 16;
    const u32 bhi = smb + bbase, blo = smb + bbase + BTILE;
#pragma unroll
    for (int ks = 0; ks < 8; ++ks) {
        const u32 kb = (u32)ks * 32;
        u32 ah[2][4], al[2][4], b[4][4];
#pragma unroll
        for (int mg = 0; mg < 2; ++mg)
            ldsm4(ah[mg][0], ah[mg][1], ah[mg][2], ah[mg][3],
                  smb + SM_AHI + a_off + (u32)mg * (16 * ROWB) + kb);
#pragma unroll
        for (int g = 0; g < 4; ++g)
            ldsm4(b[g][0], b[g][1], b[g][2], b[g][3],
                  bhi + b_off + (u32)g * (16 * ROWB) + kb);
        // hh
#pragma unroll
        for (int mg = 0; mg < 2; ++mg)
#pragma unroll
            for (int ng = 0; ng < 8; ++ng)
                mma16816(acc[mg][ng], ah[mg], b[ng >> 1][(ng & 1) * 2], b[ng >> 1][(ng & 1) * 2 + 1]);
        // lh
#pragma unroll
        for (int mg = 0; mg < 2; ++mg)
            ldsm4(al[mg][0], al[mg][1], al[mg][2], al[mg][3],
                  smb + SM_ALO + a_off + (u32)mg * (16 * ROWB) + kb);
#pragma unroll
        for (int mg = 0; mg < 2; ++mg)
#pragma unroll
            for (int ng = 0; ng < 8; ++ng)
                mma16816(acc[mg][ng], al[mg], b[ng >> 1][(ng & 1) * 2], b[ng >> 1][(ng & 1) * 2 + 1]);
        // hl
#pragma unroll
        for (int g = 0; g < 4; ++g)
            ldsm4(b[g][0], b[g][1], b[g][2], b[g][3],
                  blo + b_off + (u32)g * (16 * ROWB) + kb);
#pragma unroll
        for (int mg = 0; mg < 2; ++mg)
#pragma unroll
            for (int ng = 0; ng < 8; ++ng)
                mma16816(acc[mg][ng], ah[mg], b[ng >> 1][(ng & 1) * 2], b[ng >> 1][(ng & 1) * 2 + 1]);
    }
}

// bias + SiLU from acc -> A smem (hi/lo), zero acc
__device__ __forceinline__ void mid_epi(char* sm, float acc[2][8][4],
                                        const float* __restrict__ bias,
                                        int mbase, int nbase, int lane) {
    const int q = lane & 3, r = lane >> 2;
#pragma unroll
    for (int mg = 0; mg < 2; ++mg) {
#pragma unroll
        for (int ng = 0; ng < 8; ++ng) {
            const int col = nbase + ng * 8 + q * 2;
            const float bx = __ldg(bias + col), by = __ldg(bias + col + 1);
            const int r0 = mbase + mg * 16 + r, r1 = r0 + 8;
            float v0 = silu_f(acc[mg][ng][0] + bx);
            float v1 = silu_f(acc[mg][ng][1] + by);
            float v2 = silu_f(acc[mg][ng][2] + bx);
            float v3 = silu_f(acc[mg][ng][3] + by);
            u32 h0 = pack_bf16x2(v0, v1);
            u32 l0 = pack_bf16x2(v0 - bf_lo_f(h0), v1 - bf_hi_f(h0));
            u32 h1 = pack_bf16x2(v2, v3);
            u32 l1 = pack_bf16x2(v2 - bf_lo_f(h1), v3 - bf_hi_f(h1));
            *(u32*)(sm + SM_AHI + r0 * ROWB + col * 2) = h0;
            *(u32*)(sm + SM_ALO + r0 * ROWB + col * 2) = l0;
            *(u32*)(sm + SM_AHI + r1 * ROWB + col * 2) = h1;
            *(u32*)(sm + SM_ALO + r1 * ROWB + col * 2) = l1;
            acc[mg][ng][0] = 0.f; acc[mg][ng][1] = 0.f;
            acc[mg][ng][2] = 0.f; acc[mg][ng][3] = 0.f;
        }
    }
}

#define SVS 130  // float scratch stride; 128*130*4 = 66560 <= 2*BTILE

__device__ __forceinline__ void final_dump(char* sm, float acc[2][8][4],
                                           const float* __restrict__ b3,
                                           int mbase, int nbase, int lane) {
    float* sv = (float*)sm;
    const int q = lane & 3, r = lane >> 2;
#pragma unroll
    for (int mg = 0; mg < 2; ++mg) {
#pragma unroll
        for (int ng = 0; ng < 8; ++ng) {
            const int col = nbase + ng * 8 + q * 2;
            const float bx = __ldg(b3 + col), by = __ldg(b3 + col + 1);
            const int r0 = mbase + mg * 16 + r, r1 = r0 + 8;
            *(float2*)(sv + r0 * SVS + col) = make_float2(acc[mg][ng][0] + bx, acc[mg][ng][1] + by);
            *(float2*)(sv + r1 * SVS + col) = make_float2(acc[mg][ng][2] + bx, acc[mg][ng][3] + by);
        }
    }
}

// per-row mean/rstd stored in B0 region (dead by then)
__device__ __forceinline__ void ln_stats(char* sm, int tid) {
    if (tid < MROWS) {
        const float* sv = (float*)sm;
        float s1 = 0.f, s2 = 0.f;
#pragma unroll 16
        for (int c = 0; c < 128; c += 2) {
            float2 v = *(const float2*)(sv + tid * SVS + c);
            s1 += v.x + v.y;
            s2 += v.x * v.x + v.y * v.y;
        }
        float mean = s1 * (1.0f / 128.0f);
        float var = s2 * (1.0f / 128.0f) - mean * mean;
        ((float*)(sm + SM_B0))[tid] = mean;
        ((float*)(sm + SM_B0 + 512))[tid] = rsqrtf(var + 1e-5f);
    }
}

// ---------------------------------------------------------------------------
// Edge kernel: 128 edges/block, 256 threads (8 warps)
// ---------------------------------------------------------------------------
__global__ __launch_bounds__(NTHREADS)
void edge_kernel(const float* __restrict__ x, const int* __restrict__ eidx,
                 const float* __restrict__ ea,
                 const float* __restrict__ b1, const float* __restrict__ b2,
                 const float* __restrict__ b3,
                 const float* __restrict__ gw, const float* __restrict__ bw,
                 float* __restrict__ out_e) {
    extern __shared__ char sm[];
    const u32 smb = smem_u32(sm);
    const int tid = threadIdx.x, wid = tid >> 5, lane = tid & 31;
    const int mbase = (wid >> 1) * 32, nbase = (wid & 1) * 64;
    const int e0 = blockIdx.x * MROWS;

    float acc[2][8][4];
#pragma unroll
    for (int mg = 0; mg < 2; ++mg)
#pragma unroll
        for (int ng = 0; ng < 8; ++ng)
#pragma unroll
            for (int k = 0; k < 4; ++k) acc[mg][ng][k] = 0.f;

    // prefetch first two weight chunks
    fill_B_async(smb + SM_B0, g_we, tid);              CP_COMMIT();
    fill_B_async(smb + SM_B1, g_we + WCHUNK, tid);     CP_COMMIT();

    // ---- layer 1: 3 accumulated K=128 chunks (x[i], x[j], edge_attr) ----
    for (int s = 0; s < 3; ++s) {
        const int row = tid >> 1, qb = (tid & 1) * 16;
        const int g = (s == 0) ? __ldg(eidx + e0 + row)
                    : (s == 1) ? __ldg(eidx + NE + e0 + row)
                               : (e0 + row);
        const float4* src = (s == 2) ? (const float4*)ea : (const float4*)x;
#pragma unroll 4
        for (int i = 0; i < 16; ++i) {
            float4 v = __ldg(src + (size_t)g * 32 + qb + i);
            u64 hi, lo;
            split4(v.x, v.y, v.z, v.w, hi, lo);
            *(u64*)(sm + SM_AHI + row * ROWB + (qb + i) * 8) = hi;
            *(u64*)(sm + SM_ALO + row * ROWB + (qb + i) * 8) = lo;
        }
        CP_WAIT(1);
        __syncthreads();
        chunk_mma(smb, (s & 1) ? SM_B1 : SM_B0, acc, mbase, nbase, lane);
        __syncthreads();
        if (s + 2 < 5) {
            fill_B_async(smb + ((s & 1) ? SM_B1 : SM_B0), g_we + (size_t)(s + 2) * WCHUNK, tid);
            CP_COMMIT();
        }
    }

    // ---- layer 2 (chunk 3 -> buffer 1) ----
    mid_epi(sm, acc, b1, mbase, nbase, lane);
    CP_WAIT(1);
    __syncthreads();
    chunk_mma(smb, SM_B1, acc, mbase, nbase, lane);
    __syncthreads();

    // ---- layer 3 (chunk 4 -> buffer 0) ----
    mid_epi(sm, acc, b2, mbase, nbase, lane);
    CP_WAIT(0);
    __syncthreads();
    chunk_mma(smb, SM_B0, acc, mbase, nbase, lane);
    __syncthreads();

    // ---- final: bias3 -> LN -> residual -> store + scatter ----
    final_dump(sm, acc, b3, mbase, nbase, lane);
    __syncthreads();
    ln_stats(sm, tid);
    __syncthreads();

    {
        const int tc = tid & 15, tr = tid >> 4;
        const float* sv = (const float*)sm;
        const float* smean = (const float*)(sm + SM_B0);
        const float* srstd = (const float*)(sm + SM_B0 + 512);
        float gv[8], bv[8];
#pragma unroll
        for (int j = 0; j < 8; ++j) {
            gv[j] = __ldg(gw + tc * 8 + j);
            bv[j] = __ldg(bw + tc * 8 + j);
        }
        for (int r16 = 0; r16 < 8; ++r16) {
            const int row = r16 * 16 + tr;
            const long long gr = e0 + row;
            const float mean = smean[row], rstd = srstd[row];
            float4 ra = __ldg((const float4*)ea + gr * 32 + tc * 2);
            float4 rb = __ldg((const float4*)ea + gr * 32 + tc * 2 + 1);
            float o[8];
#pragma unroll
            for (int j = 0; j < 8; ++j)
                o[j] = (sv[row * SVS + tc * 8 + j] - mean) * rstd * gv[j] + bv[j];
            o[0] += ra.x; o[1] += ra.y; o[2] += ra.z; o[3] += ra.w;
            o[4] += rb.x; o[5] += rb.y; o[6] += rb.z; o[7] += rb.w;
            ((float4*)out_e)[gr * 32 + tc * 2]     = make_float4(o[0], o[1], o[2], o[3]);
            ((float4*)out_e)[gr * 32 + tc * 2 + 1] = make_float4(o[4], o[5], o[6], o[7]);
            const int dj = __ldg(eidx + NE + gr);
            float* ap = g_agg + (size_t)dj * 128 + tc * 8;
#pragma unroll
            for (int j = 0; j < 8; ++j) atomicAdd(ap + j, o[j]);
        }
    }
}

// ---------------------------------------------------------------------------
// Node kernel: 128 nodes/block, 256 threads
// ---------------------------------------------------------------------------
__global__ __launch_bounds__(NTHREADS)
void node_kernel(const float* __restrict__ x,
                 const float* __restrict__ b1, const float* __restrict__ b2,
                 const float* __restrict__ b3,
                 const float* __restrict__ gw, const float* __restrict__ bw,
                 float* __restrict__ out_x) {
    extern __shared__ char sm[];
    const u32 smb = smem_u32(sm);
    const int tid = threadIdx.x, wid = tid >> 5, lane = tid & 31;
    const int mbase = (wid >> 1) * 32, nbase = (wid & 1) * 64;
    const int n0 = blockIdx.x * MROWS;

    float acc[2][8][4];
#pragma unroll
    for (int mg = 0; mg < 2; ++mg)
#pragma unroll
        for (int ng = 0; ng < 8; ++ng)
#pragma unroll
            for (int k = 0; k < 4; ++k) acc[mg][ng][k] = 0.f;

    fill_B_async(smb + SM_B0, g_wn, tid);              CP_COMMIT();
    fill_B_async(smb + SM_B1, g_wn + WCHUNK, tid);     CP_COMMIT();

    // ---- layer 1: 2 accumulated K=128 chunks (x, agg) ----
    for (int s = 0; s < 2; ++s) {
        const float4* src = (s == 0) ? (const float4*)x : (const float4*)g_agg;
        const int row = tid >> 1, qb = (tid & 1) * 16;
        const int g = n0 + row;
#pragma unroll 4
        for (int i = 0; i < 16; ++i) {
            float4 v = make_float4(0.f, 0.f, 0.f, 0.f);
            if (g < NN) v = __ldg(src + (size_t)g * 32 + qb + i);
            u64 hi, lo;
            split4(v.x, v.y, v.z, v.w, hi, lo);
            *(u64*)(sm + SM_AHI + row * ROWB + (qb + i) * 8) = hi;
            *(u64*)(sm + SM_ALO + row * ROWB + (qb + i) * 8) = lo;
        }
        CP_WAIT(1);
        __syncthreads();
        chunk_mma(smb, (s & 1) ? SM_B1 : SM_B0, acc, mbase, nbase, lane);
        __syncthreads();
        if (s + 2 < 4) {
            fill_B_async(smb + ((s & 1) ? SM_B1 : SM_B0), g_wn + (size_t)(s + 2) * WCHUNK, tid);
            CP_COMMIT();
        }
    }

    // ---- layer 2 (chunk 2 -> buffer 0) ----
    mid_epi(sm, acc, b1, mbase, nbase, lane);
    CP_WAIT(1);
    __syncthreads();
    chunk_mma(smb, SM_B0, acc, mbase, nbase, lane);
    __syncthreads();

    // ---- layer 3 (chunk 3 -> buffer 1) ----
    mid_epi(sm, acc, b2, mbase, nbase, lane);
    CP_WAIT(0);
    __syncthreads();
    chunk_mma(smb, SM_B1, acc, mbase, nbase, lane);
    __syncthreads();

    final_dump(sm, acc, b3, mbase, nbase, lane);
    __syncthreads();
    ln_stats(sm, tid);
    __syncthreads();

    {
        const int tc = tid & 15, tr = tid >> 4;
        const float* sv = (const float*)sm;
        const float* smean = (const float*)(sm + SM_B0);
        const float* srstd = (const float*)(sm + SM_B0 + 512);
        float gv[8], bv[8];
#pragma unroll
        for (int j = 0; j < 8; ++j) {
            gv[j] = __ldg(gw + tc * 8 + j);
            bv[j] = __ldg(bw + tc * 8 + j);
        }
        for (int r16 = 0; r16 < 8; ++r16) {
            const int row = r16 * 16 + tr;
            const long long gr = n0 + row;
            if (gr < NN) {
                const float mean = smean[row], rstd = srstd[row];
                float4 ra = __ldg((const float4*)x + gr * 32 + tc * 2);
                float4 rb = __ldg((const float4*)x + gr * 32 + tc * 2 + 1);
                float o[8];
#pragma unroll
                for (int j = 0; j < 8; ++j)
                    o[j] = (sv[row * SVS + tc * 8 + j] - mean) * rstd * gv[j] + bv[j];
                o[0] += ra.x; o[1] += ra.y; o[2] += ra.z; o[3] += ra.w;
                o[4] += rb.x; o[5] += rb.y; o[6] += rb.z; o[7] += rb.w;
                ((float4*)out_x)[gr * 32 + tc * 2]     = make_float4(o[0], o[1], o[2], o[3]);
                ((float4*)out_x)[gr * 32 + tc * 2 + 1] = make_float4(o[4], o[5], o[6], o[7]);
            }
        }
    }
}

// ---------------------------------------------------------------------------
// Weight prep: split into bf16 hi/lo, transpose to [n][k], row stride 272B.
// ---------------------------------------------------------------------------
__global__ void prep_w(const float* __restrict__ ew1, const float* __restrict__ ew2,
                       const float* __restrict__ ew3, const float* __restrict__ nw1,
                       const float* __restrict__ nw2, const float* __restrict__ nw3) {
    int i = blockIdx.x * blockDim.x + threadIdx.x;
    if (i >= 9 * 16384) return;
    unsigned char* dst;
    float val;
    int cs = i >> 14, r = i & 16383;
    int kl = r >> 7, n = r & 127;
    if (cs < 5) {
        if (cs < 3)       val = ew1[(cs * 128 + kl) * 128 + n];
        else if (cs == 3) val = ew2[kl * 128 + n];
        else              val = ew3[kl * 128 + n];
        dst = g_we + (size_t)cs * WCHUNK;
    } else {
        int ns = cs - 5;
        if (ns < 2)       val = nw1[(ns * 128 + kl) * 128 + n];
        else if (ns == 2) val = nw2[kl * 128 + n];
        else              val = nw3[kl * 128 + n];
        dst = g_wn + (size_t)ns * WCHUNK;
    }
    u32 h = pack_bf16x2(val, 0.f);
    u32 l = pack_bf16x2(val - bf_lo_f(h), 0.f);
    *(unsigned short*)(dst + n * ROWB + kl * 2)         = (unsigned short)(h & 0xffff);
    *(unsigned short*)(dst + BTILE + n * ROWB + kl * 2) = (unsigned short)(l & 0xffff);
}

__global__ void zero_agg_kernel() {
    int i = blockIdx.x * blockDim.x + threadIdx.x;
    if (i < NN * 32)
        ((float4*)g_agg)[i] = make_float4(0.f, 0.f, 0.f, 0.f);
}

// ---------------------------------------------------------------------------
extern "C" void kernel_launch(void* const* d_in, const int* in_sizes, int n_in,
                              void* d_out, int out_size) {
    const float* x    = (const float*)d_in[0];
    const int*   eidx = (const int*)d_in[1];
    const float* ea   = (const float*)d_in[2];
    const float* ew1  = (const float*)d_in[3];
    const float* eb1  = (const float*)d_in[4];
    const float* ew2  = (const float*)d_in[5];
    const float* eb2  = (const float*)d_in[6];
    const float* ew3  = (const float*)d_in[7];
    const float* eb3  = (const float*)d_in[8];
    const float* eg   = (const float*)d_in[9];
    const float* ebt  = (const float*)d_in[10];
    const float* nw1  = (const float*)d_in[11];
    const float* nb1  = (const float*)d_in[12];
    const float* nw2  = (const float*)d_in[13];
    const float* nb2  = (const float*)d_in[14];
    const float* nw3  = (const float*)d_in[15];
    const float* nb3  = (const float*)d_in[16];
    const float* ng   = (const float*)d_in[17];
    const float* nbt  = (const float*)d_in[18];

    float* out_x = (float*)d_out;                       // [50000, 128]
    float* out_e = (float*)d_out + (size_t)NN * 128;    // [800000, 128]

    cudaFuncSetAttribute(edge_kernel, cudaFuncAttributeMaxDynamicSharedMemorySize, SM_BYTES);
    cudaFuncSetAttribute(node_kernel, cudaFuncAttributeMaxDynamicSharedMemorySize, SM_BYTES);

    zero_agg_kernel<<<(NN * 32 + 255) / 256, 256>>>();
    prep_w<<<(9 * 16384 + 255) / 256, 256>>>(ew1, ew2, ew3, nw1, nw2, nw3);
    edge_kernel<<<NE / MROWS, NTHREADS, SM_BYTES>>>(x, eidx, ea, eb1, eb2, eb3, eg, ebt, out_e);
    node_kernel<<<(NN + MROWS - 1) / MROWS, NTHREADS, SM_BYTES>>>(x, nb1, nb2, nb3, ng, nbt, out_x);
}